// round 5
// baseline (speedup 1.0000x reference)
#include <cuda_runtime.h>

// preds:   (8, 6, 4, 512, 512) fp32  -> 201,326,592 floats
// targets: (8, 6,    512, 512) ints  -> 12,582,912 values (int32 or int64-LE, detected per block)
// out = (1/8) * sum_{n,s,h,w} ( logsumexp_c preds[n,s,:,h,w] - preds[n,s,t,h,w] )
//
// Single fused kernel: grid-wide sum via per-block double atomics, the last
// block to finish writes the output and resets state (graph-replay safe).

#define HW        262144                 // 512*512 = 2^18
#define CHW       (4 * HW)               // 2^20
#define TOTAL_PX  12582912               // 48 * HW
#define THREADS   256
#define PXT       4                      // pixels per thread
#define NBLOCKS   (TOTAL_PX / (THREADS * PXT))   // 12288 exactly

static __device__ double       g_acc     = 0.0;
static __device__ unsigned int g_counter = 0u;

__device__ __forceinline__ float ce_pixel(float a, float b, float c, float d, int t) {
    float m  = fmaxf(fmaxf(a, b), fmaxf(c, d));
    float s  = __expf(a - m) + __expf(b - m) + __expf(c - m) + __expf(d - m);
    float xt = (t == 0) ? a : (t == 1) ? b : (t == 2) ? c : d;
    return m + __logf(s) - xt;
}

__global__ void __launch_bounds__(THREADS)
nims_ce_fused_kernel(const float* __restrict__ preds,
                     const int* __restrict__ tgt,
                     float* __restrict__ out) {
    __shared__ int   s_stride2;                 // 1 if targets are int64 (LE), else 0
    __shared__ float warp_sums[THREADS / 32];

    int lane = threadIdx.x & 31;
    int wid  = threadIdx.x >> 5;

    // Per-block dtype probe: int64-LE values in [0,4) => every odd 32-bit word is 0.
    // First 64 words live in L2 after the first block; one coalesced load + ballot.
    if (wid == 0) {
        int w = tgt[2 * lane + 1];
        unsigned nz = __ballot_sync(0xFFFFFFFF, w != 0);
        if (lane == 0) s_stride2 = (nz == 0u);
    }
    __syncthreads();
    int stride2 = s_stride2;

    int p0 = (blockIdx.x * THREADS + threadIdx.x) * PXT;   // < TOTAL_PX, multiple of 4
    int ns = p0 >> 18;
    int hw = p0 & (HW - 1);
    const float* base = preds + (long long)ns * CHW + hw;

    // 4 channel planes x 4 consecutive pixels: coalesced 16B loads.
    float4 v0 = *reinterpret_cast<const float4*>(base);
    float4 v1 = *reinterpret_cast<const float4*>(base + HW);
    float4 v2 = *reinterpret_cast<const float4*>(base + 2 * HW);
    float4 v3 = *reinterpret_cast<const float4*>(base + 3 * HW);

    int t0, t1, t2, t3;
    if (!stride2) {
        int4 t = *reinterpret_cast<const int4*>(tgt + p0);               // 16B aligned
        t0 = t.x; t1 = t.y; t2 = t.z; t3 = t.w;
    } else {
        const int4* tp = reinterpret_cast<const int4*>(tgt + 2LL * p0);  // 32B aligned
        int4 ta = tp[0], tb = tp[1];
        t0 = ta.x; t1 = ta.z; t2 = tb.x; t3 = tb.z;                      // low words of int64-LE
    }

    float local = ce_pixel(v0.x, v1.x, v2.x, v3.x, t0)
                + ce_pixel(v0.y, v1.y, v2.y, v3.y, t1)
                + ce_pixel(v0.z, v1.z, v2.z, v3.z, t2)
                + ce_pixel(v0.w, v1.w, v2.w, v3.w, t3);

    #pragma unroll
    for (int off = 16; off > 0; off >>= 1)
        local += __shfl_xor_sync(0xFFFFFFFF, local, off);

    if (lane == 0) warp_sums[wid] = local;
    __syncthreads();

    if (wid == 0) {
        float v = (lane < THREADS / 32) ? warp_sums[lane] : 0.0f;
        #pragma unroll
        for (int off = 4; off > 0; off >>= 1)
            v += __shfl_xor_sync(0xFFFFFFFF, v, off);

        if (lane == 0) {
            atomicAdd(&g_acc, (double)v);
            __threadfence();                               // g_acc update visible before counter
            unsigned old = atomicAdd(&g_counter, 1u);
            if (old == NBLOCKS - 1) {
                // Last block: all g_acc contributions are visible (fence + L2 atomics).
                // Read-and-reset atomically so graph replays start from clean state.
                unsigned long long bits =
                    atomicExch(reinterpret_cast<unsigned long long*>(&g_acc), 0ULL);
                double acc = __longlong_as_double((long long)bits);
                out[0] = (float)(acc * (1.0 / 8.0));        // mean over N=8
                atomicExch(&g_counter, 0u);
            }
        }
    }
}

extern "C" void kernel_launch(void* const* d_in, const int* in_sizes, int n_in,
                              void* d_out, int out_size) {
    // Role selection by size: preds is strictly the larger buffer under any
    // unit convention (elements or bytes).
    int preds_idx = 0, tgt_idx = 1;
    if (n_in >= 2 && (long long)in_sizes[1] > (long long)in_sizes[0]) {
        preds_idx = 1; tgt_idx = 0;
    }

    const float* preds = (const float*)d_in[preds_idx];
    const int*   tgt   = (const int*)d_in[tgt_idx];
    float*       out   = (float*)d_out;

    nims_ce_fused_kernel<<<NBLOCKS, THREADS>>>(preds, tgt, out);
}

// round 6
// speedup vs baseline: 1.0104x; 1.0104x over previous
#include <cuda_runtime.h>

// preds:   (8, 6, 4, 512, 512) fp32  -> 201,326,592 floats
// targets: (8, 6,    512, 512) ints  -> 12,582,912 values (int32 or int64-LE, detected per block)
// out = (1/8) * sum_{n,s,h,w} ( logsumexp_c preds[n,s,:,h,w] - preds[n,s,t,h,w] )
//
// Two launches: streaming reduce (one bare double-atomic per block, NO fence)
// + tiny finalize. Per-block fences/counters measured as a regression (R5).

#define HW        262144                 // 512*512 = 2^18
#define CHW       (4 * HW)               // 2^20
#define TOTAL_PX  12582912               // 48 * HW
#define THREADS   256
#define PXT       8                      // pixels per thread
#define NBLOCKS   (TOTAL_PX / (THREADS * PXT))   // 6144 exactly

static __device__ double g_acc = 0.0;    // reset by finalize -> graph-replay deterministic

__device__ __forceinline__ float ce_pixel(float a, float b, float c, float d, int t) {
    float m  = fmaxf(fmaxf(a, b), fmaxf(c, d));
    float s  = __expf(a - m) + __expf(b - m) + __expf(c - m) + __expf(d - m);
    float xt = (t == 0) ? a : (t == 1) ? b : (t == 2) ? c : d;
    return m + __logf(s) - xt;
}

__device__ __forceinline__ float ce_quad(float4 v0, float4 v1, float4 v2, float4 v3,
                                         int t0, int t1, int t2, int t3) {
    return ce_pixel(v0.x, v1.x, v2.x, v3.x, t0)
         + ce_pixel(v0.y, v1.y, v2.y, v3.y, t1)
         + ce_pixel(v0.z, v1.z, v2.z, v3.z, t2)
         + ce_pixel(v0.w, v1.w, v2.w, v3.w, t3);
}

__global__ void __launch_bounds__(THREADS)
nims_ce_main_kernel(const float* __restrict__ preds,
                    const int* __restrict__ tgt) {
    __shared__ int   s_stride2;                 // 1 if targets are int64 (LE), else 0
    __shared__ float warp_sums[THREADS / 32];

    int lane = threadIdx.x & 31;
    int wid  = threadIdx.x >> 5;

    // Per-block dtype probe: int64-LE values in [0,4) => every odd 32-bit word is 0.
    if (wid == 0) {
        int w = tgt[2 * lane + 1];
        unsigned nz = __ballot_sync(0xFFFFFFFF, w != 0);
        if (lane == 0) s_stride2 = (nz == 0u);
    }
    __syncthreads();
    int stride2 = s_stride2;

    int p0 = (blockIdx.x * THREADS + threadIdx.x) * PXT;   // < TOTAL_PX, multiple of 8
    int ns = p0 >> 18;
    int hw = p0 & (HW - 1);
    const float* base = preds + (long long)ns * CHW + hw;

    // 4 channel planes x 8 consecutive pixels: 8 coalesced 16B loads, all independent.
    float4 a0 = *reinterpret_cast<const float4*>(base);
    float4 a1 = *reinterpret_cast<const float4*>(base + 4);
    float4 b0 = *reinterpret_cast<const float4*>(base + HW);
    float4 b1 = *reinterpret_cast<const float4*>(base + HW + 4);
    float4 c0 = *reinterpret_cast<const float4*>(base + 2 * HW);
    float4 c1 = *reinterpret_cast<const float4*>(base + 2 * HW + 4);
    float4 d0 = *reinterpret_cast<const float4*>(base + 3 * HW);
    float4 d1 = *reinterpret_cast<const float4*>(base + 3 * HW + 4);

    int t0, t1, t2, t3, t4, t5, t6, t7;
    if (!stride2) {
        const int4* tp = reinterpret_cast<const int4*>(tgt + p0);        // 32B aligned
        int4 ta = tp[0], tb = tp[1];
        t0 = ta.x; t1 = ta.y; t2 = ta.z; t3 = ta.w;
        t4 = tb.x; t5 = tb.y; t6 = tb.z; t7 = tb.w;
    } else {
        const int4* tp = reinterpret_cast<const int4*>(tgt + 2LL * p0);  // 64B aligned
        int4 ta = tp[0], tb = tp[1], tc = tp[2], td = tp[3];
        t0 = ta.x; t1 = ta.z; t2 = tb.x; t3 = tb.z;                      // low words of int64-LE
        t4 = tc.x; t5 = tc.z; t6 = td.x; t7 = td.z;
    }

    float local = ce_quad(a0, b0, c0, d0, t0, t1, t2, t3)
                + ce_quad(a1, b1, c1, d1, t4, t5, t6, t7);

    #pragma unroll
    for (int off = 16; off > 0; off >>= 1)
        local += __shfl_xor_sync(0xFFFFFFFF, local, off);

    if (lane == 0) warp_sums[wid] = local;
    __syncthreads();

    if (wid == 0) {
        float v = (lane < THREADS / 32) ? warp_sums[lane] : 0.0f;
        #pragma unroll
        for (int off = 4; off > 0; off >>= 1)
            v += __shfl_xor_sync(0xFFFFFFFF, v, off);
        if (lane == 0)
            atomicAdd(&g_acc, (double)v);                  // bare atomic; no fence/counter
    }
}

__global__ void nims_ce_finalize_kernel(float* __restrict__ out) {
    out[0] = (float)(g_acc * (1.0 / 8.0));   // mean over N=8
    g_acc = 0.0;                              // reset for the next graph replay
}

extern "C" void kernel_launch(void* const* d_in, const int* in_sizes, int n_in,
                              void* d_out, int out_size) {
    // Role selection by size: preds is strictly the larger buffer under any
    // unit convention (elements or bytes).
    int preds_idx = 0, tgt_idx = 1;
    if (n_in >= 2 && (long long)in_sizes[1] > (long long)in_sizes[0]) {
        preds_idx = 1; tgt_idx = 0;
    }

    const float* preds = (const float*)d_in[preds_idx];
    const int*   tgt   = (const int*)d_in[tgt_idx];
    float*       out   = (float*)d_out;

    nims_ce_main_kernel<<<NBLOCKS, THREADS>>>(preds, tgt);
    nims_ce_finalize_kernel<<<1, 1>>>(out);
}

// round 7
// speedup vs baseline: 1.0127x; 1.0022x over previous
#include <cuda_runtime.h>

// preds:   (8, 6, 4, 512, 512) fp32  -> 201,326,592 floats
// targets: (8, 6,    512, 512) ints  -> 12,582,912 values (int32 or int64-LE, detected per block)
// out = (1/8) * sum_{n,s,h,w} ( logsumexp_c preds[n,s,:,h,w] - preds[n,s,t,h,w] )
//
// Structure (from measured evidence):
//   R4: two kernels, PXT=4  -> 41.5us  (main ~36us = ~7.0TB/s, near HBM roofline)
//   R5: fused fence+counter -> 43.5us  (per-block __threadfence/CCTL.IVALL regression)
//   R6: PXT=8               -> 43.1us  (L1tex-queue spread regression)
// This round: R4 structure + PDL so the finalize launch overlaps the main kernel.

#define HW        262144                 // 512*512 = 2^18
#define CHW       (4 * HW)               // 2^20
#define TOTAL_PX  12582912               // 48 * HW
#define THREADS   256
#define PXT       4                      // pixels per thread (measured optimum)
#define NBLOCKS   (TOTAL_PX / (THREADS * PXT))   // 12288 exactly

static __device__ double g_acc = 0.0;    // reset by finalize -> graph-replay deterministic

__device__ __forceinline__ float ce_pixel(float a, float b, float c, float d, int t) {
    float m  = fmaxf(fmaxf(a, b), fmaxf(c, d));
    float s  = __expf(a - m) + __expf(b - m) + __expf(c - m) + __expf(d - m);
    float xt = (t == 0) ? a : (t == 1) ? b : (t == 2) ? c : d;
    return m + __logf(s) - xt;
}

__global__ void __launch_bounds__(THREADS)
nims_ce_main_kernel(const float* __restrict__ preds,
                    const int* __restrict__ tgt) {
    __shared__ int   s_stride2;                 // 1 if targets are int64 (LE), else 0
    __shared__ float warp_sums[THREADS / 32];

    int lane = threadIdx.x & 31;
    int wid  = threadIdx.x >> 5;

    int p0 = (blockIdx.x * THREADS + threadIdx.x) * PXT;   // < TOTAL_PX, multiple of 4
    int ns = p0 >> 18;
    int hw = p0 & (HW - 1);
    const float* base = preds + (long long)ns * CHW + hw;

    // Issue the big preds stream FIRST (doesn't depend on the dtype probe).
    float4 v0 = *reinterpret_cast<const float4*>(base);
    float4 v1 = *reinterpret_cast<const float4*>(base + HW);
    float4 v2 = *reinterpret_cast<const float4*>(base + 2 * HW);
    float4 v3 = *reinterpret_cast<const float4*>(base + 3 * HW);

    // Allow the dependent (finalize) grid to begin launching; its
    // cudaGridDependencySynchronize still waits for this grid's completion.
    if (threadIdx.x == 0) cudaTriggerProgrammaticLaunchCompletion();

    // Per-block dtype probe: int64-LE values in [0,4) => every odd 32-bit word is 0.
    if (wid == 0) {
        int w = tgt[2 * lane + 1];
        unsigned nz = __ballot_sync(0xFFFFFFFF, w != 0);
        if (lane == 0) s_stride2 = (nz == 0u);
    }
    __syncthreads();

    int t0, t1, t2, t3;
    if (!s_stride2) {
        int4 t = *reinterpret_cast<const int4*>(tgt + p0);               // 16B aligned
        t0 = t.x; t1 = t.y; t2 = t.z; t3 = t.w;
    } else {
        const int4* tp = reinterpret_cast<const int4*>(tgt + 2LL * p0);  // 32B aligned
        int4 ta = tp[0], tb = tp[1];
        t0 = ta.x; t1 = ta.z; t2 = tb.x; t3 = tb.z;                      // low words of int64-LE
    }

    float local = ce_pixel(v0.x, v1.x, v2.x, v3.x, t0)
                + ce_pixel(v0.y, v1.y, v2.y, v3.y, t1)
                + ce_pixel(v0.z, v1.z, v2.z, v3.z, t2)
                + ce_pixel(v0.w, v1.w, v2.w, v3.w, t3);

    #pragma unroll
    for (int off = 16; off > 0; off >>= 1)
        local += __shfl_xor_sync(0xFFFFFFFF, local, off);

    if (lane == 0) warp_sums[wid] = local;
    __syncthreads();

    if (wid == 0) {
        float v = (lane < THREADS / 32) ? warp_sums[lane] : 0.0f;
        #pragma unroll
        for (int off = 4; off > 0; off >>= 1)
            v += __shfl_xor_sync(0xFFFFFFFF, v, off);
        if (lane == 0)
            atomicAdd(&g_acc, (double)v);                  // bare atomic; no fence/counter
    }
}

__global__ void nims_ce_finalize_kernel(float* __restrict__ out) {
    // Wait for the primary grid (all atomics visible at grid completion).
    cudaGridDependencySynchronize();
    out[0] = (float)(g_acc * (1.0 / 8.0));   // mean over N=8
    g_acc = 0.0;                              // reset for the next graph replay
}

extern "C" void kernel_launch(void* const* d_in, const int* in_sizes, int n_in,
                              void* d_out, int out_size) {
    // Role selection by size: preds is strictly the larger buffer under any
    // unit convention (elements or bytes).
    int preds_idx = 0, tgt_idx = 1;
    if (n_in >= 2 && (long long)in_sizes[1] > (long long)in_sizes[0]) {
        preds_idx = 1; tgt_idx = 0;
    }

    const float* preds = (const float*)d_in[preds_idx];
    const int*   tgt   = (const int*)d_in[tgt_idx];
    float*       out   = (float*)d_out;

    nims_ce_main_kernel<<<NBLOCKS, THREADS>>>(preds, tgt);

    // Finalize with Programmatic Dependent Launch: overlaps its launch with
    // the primary kernel; cudaGridDependencySynchronize enforces ordering.
    cudaLaunchAttribute attrs[1];
    attrs[0].id = cudaLaunchAttributeProgrammaticStreamSerialization;
    attrs[0].val.programmaticStreamSerializationAllowed = 1;

    cudaLaunchConfig_t cfg = {};
    cfg.gridDim  = dim3(1, 1, 1);
    cfg.blockDim = dim3(1, 1, 1);
    cfg.dynamicSmemBytes = 0;
    cfg.stream   = 0;               // same (legacy default) stream as the main launch
    cfg.attrs    = attrs;
    cfg.numAttrs = 1;

    cudaLaunchKernelEx(&cfg, nims_ce_finalize_kernel, out);
}